// round 6
// baseline (speedup 1.0000x reference)
#include <cuda_runtime.h>

#define BSZ   32
#define NTGT  64
#define NCLS  4
#define RM    16
#define NLVL  4

// Block layout: target blocks FIRST (start scattered gathers earliest),
// then base streaming blocks; overflow wave = tiny L3 blocks.
#define NB_TGT  512    // 8192 items / (8 warps * 2 items)
#define NB_L0   512    // 32*16384 cells / 1024
#define NB_L1   128    // 32*4096  / 1024
#define NB_L2   32     // 32*1024  / 1024
#define NB_L3   32     // 32*256   / 256
#define OFF_L0  (NB_TGT)
#define OFF_L1  (OFF_L0 + NB_L0)
#define OFF_L2  (OFF_L1 + NB_L1)
#define OFF_L3  (OFF_L2 + NB_L2)
#define NB_TOT  (OFF_L3 + NB_L3)   // 1216

#define NSLOT 32

__device__ float        g_base[NLVL * BSZ];
__device__ float        g_adjS[NSLOT];
__device__ float        g_boxS[NSLOT];
__device__ float        g_dflS[NSLOT];
__device__ unsigned int g_count;

__constant__ float c_invHW[NLVL] = {1.f/16384.f, 1.f/4096.f, 1.f/1024.f, 1.f/256.f};

// lse - logits[0] without max-subtraction (inputs ~N(0,1), args far from overflow)
__device__ __forceinline__ float lse4(float4 v) {
    float e = __expf(v.y - v.x) + __expf(v.z - v.x) + __expf(v.w - v.x);
    return __logf(1.0f + e);
}

__global__ void __launch_bounds__(256) yolo_fused_kernel(
    const float* __restrict__ c0, const float* __restrict__ c1,
    const float* __restrict__ c2, const float* __restrict__ c3,
    const float* __restrict__ r0, const float* __restrict__ r1,
    const float* __restrict__ r2, const float* __restrict__ r3,
    const float* __restrict__ targets, float* __restrict__ out)
{
    __shared__ float s24[24];
    __shared__ float fnv[BSZ];
    __shared__ int   s_last;

    int bid  = blockIdx.x;
    int tid  = threadIdx.x;
    int lane = tid & 31;
    int wrp  = tid >> 5;

    if (bid < NB_TGT) {
        // -------- target: one warp handles TWO (lvl, b, n) items --------
        int gw  = bid * 8 + wrp;                // 0..4095
        int lvl = gw >> 10;
        int rr  = gw & 1023;
        int b0  = rr >> 6;                      // itemB batch = b0 + 16
        int n   = rr & 63;

        const float* cp  = (lvl == 0) ? c0 : (lvl == 1) ? c1 : (lvl == 2) ? c2 : c3;
        const float* rp0 = (lvl == 0) ? r0 : (lvl == 1) ? r1 : (lvl == 2) ? r2 : r3;
        int   W = 128 >> lvl;
        float s = 8.0f * (float)(1 << lvl);
        int   HW = W * W;
        float inv_s = 1.0f / s;

        const float* tgA = targets + (b0 * NTGT + n) * 5;
        const float* tgB = tgA + 16 * NTGT * 5;
        float tA0 = tgA[0], ax1 = tgA[1], ay1 = tgA[2], ax2 = tgA[3], ay2 = tgA[4];
        float tB0 = tgB[0], bx1 = tgB[1], by1 = tgB[2], bx2 = tgB[3], by2 = tgB[4];
        bool vA = (tA0 >= 0.0f), vB = (tB0 >= 0.0f);
        int cidA = min(max((int)fmaxf(tA0, 0.0f), 0), NCLS - 1);
        int cidB = min(max((int)fmaxf(tB0, 0.0f), 0), NCLS - 1);

        float cxA = (ax1 + ax2) * 0.5f, cyA = (ay1 + ay2) * 0.5f;
        float cxB = (bx1 + bx2) * 0.5f, cyB = (by1 + by2) * 0.5f;
        int gxA = min(max((int)(cxA * inv_s), 0), W - 1);
        int gyA = min(max((int)(cyA * inv_s), 0), W - 1);
        int gxB = min(max((int)(cxB * inv_s), 0), W - 1);
        int gyB = min(max((int)(cyB * inv_s), 0), W - 1);
        int cellA = gyA * W + gxA, cellB = gyB * W + gxB;

        // issue all 4 scattered loads ASAP
        const float* rpA = rp0 + (size_t)b0 * 64 * HW + cellA;
        const float* rpB = rp0 + (size_t)(b0 + 16) * 64 * HW + cellB;
        float pA0 = rpA[(size_t)lane * HW];
        float pA1 = rpA[(size_t)(lane + 32) * HW];
        float pB0 = rpB[(size_t)lane * HW];
        float pB1 = rpB[(size_t)(lane + 32) * HW];

        float trA0 = (cxA - (float)gxA * s) * inv_s;
        float trA1 = (cyA - (float)gyA * s) * inv_s;
        float trA2 = (ax2 - ax1) * inv_s;
        float trA3 = (ay2 - ay1) * inv_s;
        float trB0 = (cxB - (float)gxB * s) * inv_s;
        float trB1 = (cyB - (float)gyB * s) * inv_s;
        float trB2 = (bx2 - bx1) * inv_s;
        float trB3 = (by2 - by1) * inv_s;

        float tAa = (lane < 16) ? trA0 : trA1;
        float tAb = (lane < 16) ? trA2 : trA3;
        float tBa = (lane < 16) ? trB0 : trB1;
        float tBb = (lane < 16) ? trB2 : trB3;

        float dflA = fabsf(pA0 - tAa) + fabsf(pA1 - tAb);
        float dflB = fabsf(pB0 - tBa) + fabsf(pB1 - tBb);
        #pragma unroll
        for (int off = 16; off > 0; off >>= 1) {
            dflA += __shfl_xor_sync(0xffffffffu, dflA, off);
            dflB += __shfl_xor_sync(0xffffffffu, dflB, off);
        }

        float sA0 = pA0, sA1 = pA1, sB0 = pB0, sB1 = pB1;
        #pragma unroll
        for (int off = 8; off > 0; off >>= 1) {
            sA0 += __shfl_xor_sync(0xffffffffu, sA0, off, 16);
            sA1 += __shfl_xor_sync(0xffffffffu, sA1, off, 16);
            sB0 += __shfl_xor_sync(0xffffffffu, sB0, off, 16);
            sB1 += __shfl_xor_sync(0xffffffffu, sB1, off, 16);
        }
        float bpA = 0.0f, bpB = 0.0f;
        if ((lane & 15) == 0) {
            bpA = fabsf(sA0 * (1.0f / RM) - tAa) + fabsf(sA1 * (1.0f / RM) - tAb);
            bpB = fabsf(sB0 * (1.0f / RM) - tBa) + fabsf(sB1 * (1.0f / RM) - tBb);
        }
        bpA += __shfl_xor_sync(0xffffffffu, bpA, 16);  // full sum on lanes 0 & 16
        bpB += __shfl_xor_sync(0xffffffffu, bpB, 16);

        // adj split: lane 0 handles item A, lane 16 handles item B (parallel loads)
        float invHW = 1.0f / (float)HW;
        float my_ia = 0.f, my_ib = 0.f, my_id = 0.f;
        if (lane == 0 && vA) {
            const float* cc = cp + (size_t)b0 * NCLS * HW + (size_t)cellA * NCLS;
            my_ia = (cc[0] - cc[cidA]) * invHW;
            my_ib = bpA * 0.25f;
            my_id = dflA * (1.0f / 64.0f);
        }
        if (lane == 16 && vB) {
            const float* cc = cp + (size_t)(b0 + 16) * NCLS * HW + (size_t)cellB * NCLS;
            my_ia = (cc[0] - cc[cidB]) * invHW;
            my_ib = bpB * 0.25f;
            my_id = dflB * (1.0f / 64.0f);
        }
        my_ia += __shfl_xor_sync(0xffffffffu, my_ia, 16);
        my_ib += __shfl_xor_sync(0xffffffffu, my_ib, 16);
        my_id += __shfl_xor_sync(0xffffffffu, my_id, 16);
        if (lane == 0) { s24[wrp] = my_ia; s24[8 + wrp] = my_ib; s24[16 + wrp] = my_id; }
        __syncthreads();
        if (tid == 0) {
            float a = 0.f, bb = 0.f, d = 0.f;
            #pragma unroll
            for (int i = 0; i < 8; i++) { a += s24[i]; bb += s24[8+i]; d += s24[16+i]; }
            int slot = bid & (NSLOT - 1);
            atomicAdd(&g_adjS[slot], a);
            atomicAdd(&g_boxS[slot], bb);
            atomicAdd(&g_dflS[slot], d);
        }
    } else {
        // ---------------- base: streaming logsumexp over cls ----------------
        float sum = 0.0f;
        int gidx;   // lvl*32 + b
        if (bid < OFF_L1) {                       // L0: 1024 cells, 4/thread
            const float4* v4 = (const float4*)c0;
            int bl = bid - OFF_L0;
            int start = bl << 10;
            #pragma unroll
            for (int i = 0; i < 4; i++) sum += lse4(v4[start + (i << 8) + tid]);
            gidx = bl >> 4;                       // 16 blocks per batch
        } else if (bid < OFF_L2) {                // L1: 1024 cells, 4/thread
            const float4* v4 = (const float4*)c1;
            int bl = bid - OFF_L1;
            int start = bl << 10;
            #pragma unroll
            for (int i = 0; i < 4; i++) sum += lse4(v4[start + (i << 8) + tid]);
            gidx = 32 + (bl >> 2);                // 4 blocks per batch
        } else if (bid < OFF_L3) {                // L2: 1024 cells, 4/thread
            const float4* v4 = (const float4*)c2;
            int bl = bid - OFF_L2;
            int start = bl << 10;
            #pragma unroll
            for (int i = 0; i < 4; i++) sum += lse4(v4[start + (i << 8) + tid]);
            gidx = 64 + bl;                       // 1 block per batch
        } else {                                  // L3: 256 cells, 1/thread
            const float4* v4 = (const float4*)c3;
            int bl = bid - OFF_L3;
            sum = lse4(v4[(bl << 8) + tid]);
            gidx = 96 + bl;
        }
        #pragma unroll
        for (int off = 16; off > 0; off >>= 1)
            sum += __shfl_xor_sync(0xffffffffu, sum, off);
        if (lane == 0) s24[wrp] = sum;
        __syncthreads();
        if (tid == 0) {
            float t = 0.f;
            #pragma unroll
            for (int i = 0; i < 8; i++) t += s24[i];
            atomicAdd(&g_base[gidx], t);
        }
    }

    // ---------------- grid-completion handshake ----------------
    __syncthreads();
    __threadfence();
    if (tid == 0) {
        unsigned int old = atomicAdd(&g_count, 1u);
        s_last = (old == NB_TOT - 1) ? 1 : 0;
    }
    __syncthreads();
    if (!s_last) return;

    // ---------------- finalize (last block only) ----------------
    if (tid < BSZ) {
        int cnt = 0;
        for (int n = 0; n < NTGT; n++)
            cnt += (targets[(tid * NTGT + n) * 5] >= 0.0f) ? 1 : 0;
        fnv[tid] = (float)cnt;
    }
    __syncthreads();

    float clsP = 0.f, boxP = 0.f, dflP = 0.f;
    if (tid < NLVL * BSZ)
        clsP = __ldcg(&g_base[tid]) * c_invHW[tid >> 5] * fnv[tid & 31];
    else if (tid < NLVL * BSZ + NSLOT)
        clsP = __ldcg(&g_adjS[tid - NLVL * BSZ]);
    if (tid < NSLOT) {
        boxP = __ldcg(&g_boxS[tid]);
        dflP = __ldcg(&g_dflS[tid]);
    }
    #pragma unroll
    for (int off = 16; off > 0; off >>= 1) {
        clsP += __shfl_xor_sync(0xffffffffu, clsP, off);
        boxP += __shfl_xor_sync(0xffffffffu, boxP, off);
        dflP += __shfl_xor_sync(0xffffffffu, dflP, off);
    }
    if (lane == 0) { s24[wrp] = clsP; s24[8 + wrp] = boxP; s24[16 + wrp] = dflP; }
    __syncthreads();
    if (tid == 0) {
        float cls = 0.f, box = 0.f, dfl = 0.f;
        #pragma unroll
        for (int i = 0; i < 8; i++) { cls += s24[i]; box += s24[8+i]; dfl += s24[16+i]; }
        out[0] = 0.3f * cls + 8.0f * box + 1.5f * dfl;
        out[1] = cls;
        out[2] = box;
        out[3] = dfl;
        g_count = 0u;
    }
    if (tid < NLVL * BSZ) g_base[tid] = 0.0f;
    if (tid < NSLOT) { g_adjS[tid] = 0.0f; g_boxS[tid] = 0.0f; g_dflS[tid] = 0.0f; }
}

// ---------------------------------------------------------------------------
extern "C" void kernel_launch(void* const* d_in, const int* in_sizes, int n_in,
                              void* d_out, int out_size) {
    const float* cls[NLVL];
    const float* reg[NLVL];
    bool interleaved = (in_sizes[1] > in_sizes[0]);
    if (interleaved) {
        for (int l = 0; l < NLVL; l++) {
            cls[l] = (const float*)d_in[2 * l];
            reg[l] = (const float*)d_in[2 * l + 1];
        }
    } else {
        for (int l = 0; l < NLVL; l++) {
            cls[l] = (const float*)d_in[l];
            reg[l] = (const float*)d_in[NLVL + l];
        }
    }
    const float* targets = (const float*)d_in[8];
    float* out = (float*)d_out;

    yolo_fused_kernel<<<NB_TOT, 256>>>(cls[0], cls[1], cls[2], cls[3],
                                       reg[0], reg[1], reg[2], reg[3],
                                       targets, out);
}

// round 8
// speedup vs baseline: 1.0752x; 1.0752x over previous
#include <cuda_runtime.h>
#include <cuda_fp16.h>

#define BSZ   32
#define NTGT  64
#define NCLS  4
#define RM    16
#define NLVL  4

// Layout: target blocks first (start scattered gathers earliest), then base.
#define NB_TGT  512    // 8192 items / (8 warps * 2 items)
#define NB_L0   256    // 32*16384 cells / 2048
#define NB_L1   64     // 32*4096  / 2048
#define NB_L2   32     // 32*1024  / 1024
#define NB_L3   32     // 32*256   / 256
#define OFF_L0  (NB_TGT)
#define OFF_L1  (OFF_L0 + NB_L0)
#define OFF_L2  (OFF_L1 + NB_L1)
#define OFF_L3  (OFF_L2 + NB_L2)
#define NB_TOT  (OFF_L3 + NB_L3)   // 896

#define NSLOT 32
#define LOG2E 1.44269504088896f
#define LN2   0.69314718055995f

// g_base accumulates sum over cells of log2(S'), S' = S/4,
// i.e. (lse - x0)/ln2 - 2 per cell. Finalize re-adds the constants.
__device__ float        g_base[NLVL * BSZ];
__device__ float        g_adjS[NSLOT];
__device__ float        g_boxS[NSLOT];
__device__ float        g_dflS[NSLOT];
__device__ unsigned int g_count;

__constant__ float c_invHW[NLVL] = {1.f/16384.f, 1.f/4096.f, 1.f/1024.f, 1.f/256.f};

// Process a PAIR of cells (va, vb): multiply running product m by S'_A and S'_B,
// where S' = 0.25 + sum_j 2^(d_j*log2e - 2) = (e^0+e^d1+e^d2+e^d3)/4.
// Uses one f16x2 EX2 per packed pair of diffs -> 1.5 MUFU per cell.
__device__ __forceinline__ void lse_pair(float4 va, float4 vb, float& m, int& E,
                                         __half2 quarter) {
    float uA = fmaf(va.x, -LOG2E, -2.0f);
    float uB = fmaf(vb.x, -LOG2E, -2.0f);
    float tA1 = fmaf(va.y, LOG2E, uA);
    float tA2 = fmaf(va.z, LOG2E, uA);
    float tA3 = fmaf(va.w, LOG2E, uA);
    float tB1 = fmaf(vb.y, LOG2E, uB);
    float tB2 = fmaf(vb.z, LOG2E, uB);
    float tB3 = fmaf(vb.w, LOG2E, uB);
    __half2 e1 = h2exp2(__floats2half2_rn(tA1, tB1));   // lo = cell A
    __half2 e2 = h2exp2(__floats2half2_rn(tA2, tB2));
    __half2 e3 = h2exp2(__floats2half2_rn(tA3, tB3));
    __half2 S2 = __hadd2(__hadd2(e1, e2), __hadd2(e3, quarter));
    float2 Sf = __half22float2(S2);
    m *= Sf.x;
    m *= Sf.y;
    // renormalize: pull exponent out of m into E (keeps f32 product exact-ish)
    unsigned bits = __float_as_uint(m);
    E += (int)(bits >> 23) - 127;
    m = __uint_as_float((bits & 0x007FFFFFu) | 0x3F800000u);
}

__global__ void __launch_bounds__(256) yolo_fused_kernel(
    const float* __restrict__ c0, const float* __restrict__ c1,
    const float* __restrict__ c2, const float* __restrict__ c3,
    const float* __restrict__ r0, const float* __restrict__ r1,
    const float* __restrict__ r2, const float* __restrict__ r3,
    const float* __restrict__ targets, float* __restrict__ out)
{
    __shared__ float s24[24];
    __shared__ float fnv[BSZ];
    __shared__ int   s_last;

    int bid  = blockIdx.x;
    int tid  = threadIdx.x;
    int lane = tid & 31;
    int wrp  = tid >> 5;

    if (bid < NB_TGT) {
        // -------- target: one warp handles TWO (lvl, b, n) items --------
        int gw  = bid * 8 + wrp;                // 0..4095
        int lvl = gw >> 10;
        int rr  = gw & 1023;
        int b0  = rr >> 6;                      // itemB batch = b0 + 16
        int n   = rr & 63;

        const float* cp  = (lvl == 0) ? c0 : (lvl == 1) ? c1 : (lvl == 2) ? c2 : c3;
        const float* rp0 = (lvl == 0) ? r0 : (lvl == 1) ? r1 : (lvl == 2) ? r2 : r3;
        int   W = 128 >> lvl;
        float s = 8.0f * (float)(1 << lvl);
        int   HW = W * W;
        float inv_s = 1.0f / s;

        const float* tgA = targets + (b0 * NTGT + n) * 5;
        const float* tgB = tgA + 16 * NTGT * 5;
        float tA0 = tgA[0], ax1 = tgA[1], ay1 = tgA[2], ax2 = tgA[3], ay2 = tgA[4];
        float tB0 = tgB[0], bx1 = tgB[1], by1 = tgB[2], bx2 = tgB[3], by2 = tgB[4];
        bool vA = (tA0 >= 0.0f), vB = (tB0 >= 0.0f);
        int cidA = min(max((int)fmaxf(tA0, 0.0f), 0), NCLS - 1);
        int cidB = min(max((int)fmaxf(tB0, 0.0f), 0), NCLS - 1);

        float cxA = (ax1 + ax2) * 0.5f, cyA = (ay1 + ay2) * 0.5f;
        float cxB = (bx1 + bx2) * 0.5f, cyB = (by1 + by2) * 0.5f;
        int gxA = min(max((int)(cxA * inv_s), 0), W - 1);
        int gyA = min(max((int)(cyA * inv_s), 0), W - 1);
        int gxB = min(max((int)(cxB * inv_s), 0), W - 1);
        int gyB = min(max((int)(cyB * inv_s), 0), W - 1);
        int cellA = gyA * W + gxA, cellB = gyB * W + gxB;

        const float* rpA = rp0 + (size_t)b0 * 64 * HW + cellA;
        const float* rpB = rp0 + (size_t)(b0 + 16) * 64 * HW + cellB;
        float pA0 = rpA[(size_t)lane * HW];
        float pA1 = rpA[(size_t)(lane + 32) * HW];
        float pB0 = rpB[(size_t)lane * HW];
        float pB1 = rpB[(size_t)(lane + 32) * HW];

        float trA0 = (cxA - (float)gxA * s) * inv_s;
        float trA1 = (cyA - (float)gyA * s) * inv_s;
        float trA2 = (ax2 - ax1) * inv_s;
        float trA3 = (ay2 - ay1) * inv_s;
        float trB0 = (cxB - (float)gxB * s) * inv_s;
        float trB1 = (cyB - (float)gyB * s) * inv_s;
        float trB2 = (bx2 - bx1) * inv_s;
        float trB3 = (by2 - by1) * inv_s;

        float tAa = (lane < 16) ? trA0 : trA1;
        float tAb = (lane < 16) ? trA2 : trA3;
        float tBa = (lane < 16) ? trB0 : trB1;
        float tBb = (lane < 16) ? trB2 : trB3;

        float dflA = fabsf(pA0 - tAa) + fabsf(pA1 - tAb);
        float dflB = fabsf(pB0 - tBa) + fabsf(pB1 - tBb);
        #pragma unroll
        for (int off = 16; off > 0; off >>= 1) {
            dflA += __shfl_xor_sync(0xffffffffu, dflA, off);
            dflB += __shfl_xor_sync(0xffffffffu, dflB, off);
        }

        float sA0 = pA0, sA1 = pA1, sB0 = pB0, sB1 = pB1;
        #pragma unroll
        for (int off = 8; off > 0; off >>= 1) {
            sA0 += __shfl_xor_sync(0xffffffffu, sA0, off, 16);
            sA1 += __shfl_xor_sync(0xffffffffu, sA1, off, 16);
            sB0 += __shfl_xor_sync(0xffffffffu, sB0, off, 16);
            sB1 += __shfl_xor_sync(0xffffffffu, sB1, off, 16);
        }
        float bpA = 0.0f, bpB = 0.0f;
        if ((lane & 15) == 0) {
            bpA = fabsf(sA0 * (1.0f / RM) - tAa) + fabsf(sA1 * (1.0f / RM) - tAb);
            bpB = fabsf(sB0 * (1.0f / RM) - tBa) + fabsf(sB1 * (1.0f / RM) - tBb);
        }
        bpA += __shfl_xor_sync(0xffffffffu, bpA, 16);  // full sums on lanes 0 & 16
        bpB += __shfl_xor_sync(0xffffffffu, bpB, 16);

        // adj split: lane 0 -> item A, lane 16 -> item B (parallel cls loads)
        float invHW = 1.0f / (float)HW;
        float my_ia = 0.f, my_ib = 0.f, my_id = 0.f;
        if (lane == 0 && vA) {
            const float* cc = cp + (size_t)b0 * NCLS * HW + (size_t)cellA * NCLS;
            my_ia = (cc[0] - cc[cidA]) * invHW;
            my_ib = bpA * 0.25f;
            my_id = dflA * (1.0f / 64.0f);
        }
        if (lane == 16 && vB) {
            const float* cc = cp + (size_t)(b0 + 16) * NCLS * HW + (size_t)cellB * NCLS;
            my_ia = (cc[0] - cc[cidB]) * invHW;
            my_ib = bpB * 0.25f;
            my_id = dflB * (1.0f / 64.0f);
        }
        my_ia += __shfl_xor_sync(0xffffffffu, my_ia, 16);
        my_ib += __shfl_xor_sync(0xffffffffu, my_ib, 16);
        my_id += __shfl_xor_sync(0xffffffffu, my_id, 16);
        if (lane == 0) { s24[wrp] = my_ia; s24[8 + wrp] = my_ib; s24[16 + wrp] = my_id; }
        __syncthreads();
        if (tid == 0) {
            float a = 0.f, bb = 0.f, d = 0.f;
            #pragma unroll
            for (int i = 0; i < 8; i++) { a += s24[i]; bb += s24[8+i]; d += s24[16+i]; }
            int slot = bid & (NSLOT - 1);
            atomicAdd(&g_adjS[slot], a);
            atomicAdd(&g_boxS[slot], bb);
            atomicAdd(&g_dflS[slot], d);
        }
    } else {
        // -------- base: streaming log-sum-exp via f16x2 EX2 + product-log ----
        float sum = 0.0f;          // accumulates log2(S') per thread
        float m = 1.0f;
        int   E = 0;
        __half2 quarter = __float2half2_rn(0.25f);
        int gidx;
        if (bid < OFF_L1) {                       // L0: 2048 cells, 8/thread
            const float4* v4 = (const float4*)c0;
            int bl = bid - OFF_L0;
            int start = bl << 11;
            #pragma unroll
            for (int i = 0; i < 4; i++) {
                float4 va = v4[start + ((2*i)   << 8) + tid];
                float4 vb = v4[start + ((2*i+1) << 8) + tid];
                lse_pair(va, vb, m, E, quarter);
            }
            gidx = bl >> 3;                       // 8 blocks per batch
        } else if (bid < OFF_L2) {                // L1: 2048 cells, 8/thread
            const float4* v4 = (const float4*)c1;
            int bl = bid - OFF_L1;
            int start = bl << 11;
            #pragma unroll
            for (int i = 0; i < 4; i++) {
                float4 va = v4[start + ((2*i)   << 8) + tid];
                float4 vb = v4[start + ((2*i+1) << 8) + tid];
                lse_pair(va, vb, m, E, quarter);
            }
            gidx = 32 + (bl >> 1);                // 2 blocks per batch
        } else if (bid < OFF_L3) {                // L2: 1024 cells, 4/thread
            const float4* v4 = (const float4*)c2;
            int bl = bid - OFF_L2;
            int start = bl << 10;
            #pragma unroll
            for (int i = 0; i < 2; i++) {
                float4 va = v4[start + ((2*i)   << 8) + tid];
                float4 vb = v4[start + ((2*i+1) << 8) + tid];
                lse_pair(va, vb, m, E, quarter);
            }
            gidx = 64 + bl;
        } else {                                  // L3: 256 cells, 1/thread (f32)
            const float4* v4 = (const float4*)c3;
            int bl = bid - OFF_L3;
            float4 v = v4[(bl << 8) + tid];
            float e = __expf(v.y - v.x) + __expf(v.z - v.x) + __expf(v.w - v.x);
            // convert ln(S) to log2(S') = ln(S)/ln2 - 2 units
            sum = fmaf(__logf(1.0f + e), LOG2E, -2.0f);
            gidx = 96 + bl;
        }
        if (bid < OFF_L3) sum = __log2f(m) + (float)E;

        #pragma unroll
        for (int off = 16; off > 0; off >>= 1)
            sum += __shfl_xor_sync(0xffffffffu, sum, off);
        if (lane == 0) s24[wrp] = sum;
        __syncthreads();
        if (tid == 0) {
            float t = 0.f;
            #pragma unroll
            for (int i = 0; i < 8; i++) t += s24[i];
            atomicAdd(&g_base[gidx], t);
        }
    }

    // ---------------- grid-completion handshake ----------------
    __syncthreads();
    __threadfence();
    if (tid == 0) {
        unsigned int old = atomicAdd(&g_count, 1u);
        s_last = (old == NB_TOT - 1) ? 1 : 0;
    }
    __syncthreads();
    if (!s_last) return;

    // ---------------- finalize (last block only) ----------------
    if (tid < BSZ) {
        int cnt = 0;
        for (int n = 0; n < NTGT; n++)
            cnt += (targets[(tid * NTGT + n) * 5] >= 0.0f) ? 1 : 0;
        fnv[tid] = (float)cnt;
    }
    __syncthreads();

    float clsP = 0.f, boxP = 0.f, dflP = 0.f;
    if (tid < NLVL * BSZ) {
        // base_mean_ln = ln2 * (sum_log2' * invHW) + 2*ln2   (per-cell +2 shift)
        float bm = fmaf(LN2 * __ldcg(&g_base[tid]), c_invHW[tid >> 5], 2.0f * LN2);
        clsP = bm * fnv[tid & 31];
    } else if (tid < NLVL * BSZ + NSLOT) {
        clsP = __ldcg(&g_adjS[tid - NLVL * BSZ]);
    }
    if (tid < NSLOT) {
        boxP = __ldcg(&g_boxS[tid]);
        dflP = __ldcg(&g_dflS[tid]);
    }
    #pragma unroll
    for (int off = 16; off > 0; off >>= 1) {
        clsP += __shfl_xor_sync(0xffffffffu, clsP, off);
        boxP += __shfl_xor_sync(0xffffffffu, boxP, off);
        dflP += __shfl_xor_sync(0xffffffffu, dflP, off);
    }
    if (lane == 0) { s24[wrp] = clsP; s24[8 + wrp] = boxP; s24[16 + wrp] = dflP; }
    __syncthreads();
    if (tid == 0) {
        float cls = 0.f, box = 0.f, dfl = 0.f;
        #pragma unroll
        for (int i = 0; i < 8; i++) { cls += s24[i]; box += s24[8+i]; dfl += s24[16+i]; }
        out[0] = 0.3f * cls + 8.0f * box + 1.5f * dfl;
        out[1] = cls;
        out[2] = box;
        out[3] = dfl;
        g_count = 0u;
    }
    if (tid < NLVL * BSZ) g_base[tid] = 0.0f;
    if (tid < NSLOT) { g_adjS[tid] = 0.0f; g_boxS[tid] = 0.0f; g_dflS[tid] = 0.0f; }
}

// ---------------------------------------------------------------------------
extern "C" void kernel_launch(void* const* d_in, const int* in_sizes, int n_in,
                              void* d_out, int out_size) {
    const float* cls[NLVL];
    const float* reg[NLVL];
    bool interleaved = (in_sizes[1] > in_sizes[0]);
    if (interleaved) {
        for (int l = 0; l < NLVL; l++) {
            cls[l] = (const float*)d_in[2 * l];
            reg[l] = (const float*)d_in[2 * l + 1];
        }
    } else {
        for (int l = 0; l < NLVL; l++) {
            cls[l] = (const float*)d_in[l];
            reg[l] = (const float*)d_in[NLVL + l];
        }
    }
    const float* targets = (const float*)d_in[8];
    float* out = (float*)d_out;

    yolo_fused_kernel<<<NB_TOT, 256>>>(cls[0], cls[1], cls[2], cls[3],
                                       reg[0], reg[1], reg[2], reg[3],
                                       targets, out);
}